// round 14
// baseline (speedup 1.0000x reference)
#include <cuda_runtime.h>
#include <cuda_fp16.h>
#include <math.h>

#define HH 512
#define WW 512
#define BB 8
#define KK 16
#define HW (HH*WW)
#define BK (BB*KK)
#define NBU 2048                 // u-bins (uniform in s*diff^2)
#define NB  2048                 // err-bins (scan space, err coord = d*NB)
#define UMAX 12.0f
#define SPLIT 4
#define MSPLIT 4
#define INV_GRID (1.0f/1023.0f)
#define LOG2E 1.4426950408889634f

// All replay-zeroed state in ONE struct -> one memset node.
struct ZeroState {
    unsigned int uhist[BK][NBU];   // nonmask, u-binned
    unsigned int mhist[BK][NB];    // mask, exact err-binned
    float cnt[BK], scol[BK], srow[BK], ss[BK], ss2[BK];
    float seedloss[BB], instloss[BB];
    unsigned int done;
};
__device__ ZeroState g_z;
__device__ __half2       g_emb[BB*HW];   // (ex, ey) per pixel, f16x2
__device__ float         g_seed[BB*HW];
__device__ unsigned char g_mk[BB*HW];

__device__ __forceinline__ float tanh_fast(float x){
    float y; asm("tanh.approx.f32 %0, %1;" : "=f"(y) : "f"(x)); return y;
}

// ---------------------------------------------------------------------------
// Prep: emb = tanh + xy (stored f16x2), seed = sigmoid, mask byte, bg seed.
// is64 detected inline: odd uint32 words of first 16 int64s all zero <=> int64.
// ---------------------------------------------------------------------------
__global__ void __launch_bounds__(512) prep_kernel(const float* __restrict__ pred,
                                                   const void* __restrict__ instp,
                                                   const void* __restrict__ labp) {
    __shared__ float s_bg[16];
    const int tid = threadIdx.x;
    const int b = blockIdx.y;
    const int i4 = blockIdx.x * 2048 + tid * 4;
    const float* pb = pred + (size_t)b * 4 * HW;
    const size_t off = (size_t)b * HW + i4;

    const unsigned* rr = (const unsigned*)instp;
    unsigned any = 0;
    #pragma unroll
    for (int i = 1; i < 32; i += 2) any |= rr[i];
    const int is64 = any ? 0 : 1;

    float4 p0 = *(const float4*)(pb + i4);
    float4 p1 = *(const float4*)(pb + HW + i4);
    float4 p3 = *(const float4*)(pb + 3*HW + i4);

    int inst[4], lab[4];
    if (is64) {
        const int4* ip = (const int4*)instp;
        const int4* lp = (const int4*)labp;
        size_t q = off >> 1;
        int4 a = ip[q],   c = ip[q+1];
        int4 d0 = lp[q],  d1 = lp[q+1];
        inst[0]=a.x; inst[1]=a.z; inst[2]=c.x; inst[3]=c.z;
        lab[0]=d0.x; lab[1]=d0.z; lab[2]=d1.x; lab[3]=d1.z;
    } else {
        int4 a  = ((const int4*)instp)[off>>2];
        int4 d0 = ((const int4*)labp)[off>>2];
        inst[0]=a.x; inst[1]=a.y; inst[2]=a.z; inst[3]=a.w;
        lab[0]=d0.x; lab[1]=d0.y; lab[2]=d0.z; lab[3]=d0.w;
    }

    float y  = (float)(i4 >> 9) * INV_GRID;
    float xb = (float)(i4 & (WW-1)) * INV_GRID;

    const float* p0a = (const float*)&p0;
    const float* p1a = (const float*)&p1;
    const float* p3a = (const float*)&p3;
    __half2 eh[4];
    float sd[4];
    #pragma unroll
    for (int j = 0; j < 4; j++) {
        float ex = tanh_fast(p0a[j]) + (xb + j*INV_GRID);
        float ey = tanh_fast(p1a[j]) + y;
        eh[j] = __floats2half2_rn(ex, ey);
        sd[j] = fmaf(tanh_fast(0.5f*p3a[j]), 0.5f, 0.5f);
    }
    *(uint4*)(g_emb+off) = *(const uint4*)eh;
    *(float4*)(g_seed+off) = make_float4(sd[0],sd[1],sd[2],sd[3]);

    unsigned mk4 = 0;
    float bg = 0.f;
    #pragma unroll
    for (int j = 0; j < 4; j++) {
        unsigned m = (lab[j]==1 && inst[j]>=1 && inst[j]<=KK) ? (unsigned)inst[j] : 0u;
        mk4 |= m << (8*j);
        if (lab[j]==0) bg += sd[j]*sd[j];
    }
    *(unsigned*)(g_mk+off) = mk4;

    #pragma unroll
    for (int o = 16; o; o >>= 1) bg += __shfl_down_sync(0xffffffffu, bg, o);
    if ((tid & 31) == 0) s_bg[tid>>5] = bg;
    __syncthreads();
    if (tid == 0) {
        float t = 0.f;
        #pragma unroll
        for (int w = 0; w < 16; w++) t += s_bg[w];
        atomicAdd(&g_z.seedloss[b], t);
    }
}

// ---------------------------------------------------------------------------
// Moments: per (b,k), register accumulation, 16 px/thread skip-fast.
// ---------------------------------------------------------------------------
__global__ void __launch_bounds__(512) moments_kernel(const float* __restrict__ pred){
    __shared__ float s_red[16*5];
    const int bk = blockIdx.y;
    const int b = bk >> 4;
    const unsigned kid4 = ((unsigned)(bk & 15) + 1u) * 0x01010101u;
    const int tid = threadIdx.x;
    const float* p2 = pred + (size_t)b*4*HW + 2*HW;
    const unsigned char* mk = g_mk + (size_t)b*HW;
    const int pbase = blockIdx.x * (HW / MSPLIT);

    float cnt=0.f, scol=0.f, srow=0.f, ss=0.f, ss2=0.f;

    #pragma unroll
    for (int g = 0; g < (HW/MSPLIT)/(512*16); g++){   // 8 iterations
        int i16 = pbase + (g*512 + tid)*16;
        uint4 m = *(const uint4*)(mk + i16);
        unsigned e[4];
        e[0] = __vcmpeq4(m.x, kid4); e[1] = __vcmpeq4(m.y, kid4);
        e[2] = __vcmpeq4(m.z, kid4); e[3] = __vcmpeq4(m.w, kid4);
        if (e[0]|e[1]|e[2]|e[3]){
            float row = (float)(i16 >> 9);
            int colb = i16 & (WW-1);
            #pragma unroll
            for (int q = 0; q < 4; q++){
                if (!e[q]) continue;
                #pragma unroll
                for (int j = 0; j < 4; j++){
                    if ((e[q] >> (8*j)) & 1u){
                        int px = q*4 + j;
                        float v = p2[i16+px];
                        cnt += 1.f; scol += (float)(colb+px); srow += row;
                        ss += v; ss2 = fmaf(v, v, ss2);
                    }
                }
            }
        }
    }
    int lane = tid & 31, wid = tid >> 5;
    #pragma unroll
    for (int o = 16; o; o >>= 1){
        cnt += __shfl_down_sync(0xffffffffu,cnt ,o);
        scol+= __shfl_down_sync(0xffffffffu,scol,o);
        srow+= __shfl_down_sync(0xffffffffu,srow,o);
        ss  += __shfl_down_sync(0xffffffffu,ss  ,o);
        ss2 += __shfl_down_sync(0xffffffffu,ss2 ,o);
    }
    if (lane == 0){
        s_red[wid*5+0]=cnt; s_red[wid*5+1]=scol; s_red[wid*5+2]=srow;
        s_red[wid*5+3]=ss;  s_red[wid*5+4]=ss2;
    }
    __syncthreads();
    if (tid == 0){
        float a0=0,a1=0,a2=0,a3=0,a4=0;
        #pragma unroll
        for (int w=0;w<16;w++){a0+=s_red[w*5];a1+=s_red[w*5+1];a2+=s_red[w*5+2];a3+=s_red[w*5+3];a4+=s_red[w*5+4];}
        if (a0 > 0.f){
            atomicAdd(&g_z.cnt[bk], a0); atomicAdd(&g_z.scol[bk], a1);
            atomicAdd(&g_z.srow[bk], a2); atomicAdd(&g_z.ss[bk],  a3);
            atomicAdd(&g_z.ss2[bk],  a4);
        }
    }
}

// ---------------------------------------------------------------------------
// Hist: nonmask -> u-bins via plain smem atomics into TWO sub-histograms
// (warp parity) to halve conflict degree; mask (~3%) -> exact err-bins via
// rare global atomics + seed term. emb f16x2 -> one LDG.128 per 4 px.
// ---------------------------------------------------------------------------
__global__ void __launch_bounds__(512,4) lovasz_hist_kernel(){
    __shared__ unsigned hu[2*NBU];
    __shared__ float s_red[16];
    const int bs = blockIdx.x;
    const int bk = bs / SPLIT;
    const int part = bs % SPLIT;
    const int b = bk >> 4;
    const int tid = threadIdx.x;

    for (int i = tid; i < 2*NBU; i += 512) hu[i] = 0u;

    const float cntk = g_z.cnt[bk];
    const float safe = fmaxf(cntk, 1.f);
    const float mean = g_z.ss[bk] / safe;
    const float cx = (g_z.scol[bk] / safe) * INV_GRID;
    const float cy = (g_z.srow[bk] / safe) * INV_GRID;
    const float sE = expf(10.f * mean);
    const float sq  = sqrtf(sE * ((float)NBU / UMAX)); // binf = |e*sq - c*sq|^2
    const float oxs = -cx * sq;
    const float oys = -cy * sq;
    const float KM  = -(UMAX / (float)NBU) * LOG2E;    // d = exp2f(binf*KM)
    const unsigned kid4 = ((unsigned)(bk & 15) + 1u) * 0x01010101u;
    __syncthreads();

    const __half2* __restrict__ emb = g_emb + (size_t)b*HW;
    const float*  __restrict__ seedp= g_seed + (size_t)b*HW;
    const unsigned char* __restrict__ mk = g_mk + (size_t)b*HW;
    unsigned* __restrict__ mh = g_z.mhist[bk];
    unsigned* hup = hu + ((tid >> 5) & 1) * NBU;   // warp-parity sub-histogram
    const int pbase = part * (HW/SPLIT);
    float seedacc = 0.f;

    #pragma unroll 1
    for (int g = 0; g < (HW/SPLIT)/(512*4); g++){   // 32 iterations
        int i4 = pbase + (g*512 + tid)*4;
        uint4 ev = *(const uint4*)(emb + i4);       // 4 px, f16x2 each
        unsigned m4 = *(const unsigned*)(mk + i4);
        unsigned eq = __vcmpeq4(m4, kid4);
        float2 e0 = __half22float2(*(const __half2*)&ev.x);
        float2 e1 = __half22float2(*(const __half2*)&ev.y);
        float2 e2 = __half22float2(*(const __half2*)&ev.z);
        float2 e3 = __half22float2(*(const __half2*)&ev.w);
        float exs[4] = {e0.x, e1.x, e2.x, e3.x};
        float eys[4] = {e0.y, e1.y, e2.y, e3.y};
        #pragma unroll
        for (int j = 0; j < 4; j++){
            float dxs = fmaf(exs[j], sq, oxs);
            float dys = fmaf(eys[j], sq, oys);
            float binf = fmaf(dxs, dxs, dys*dys);
            if (!((eq >> (8*j)) & 1u)){
                int bin = min((int)binf, NBU-1);
                atomicAdd(&hup[bin], 1u);
            } else {
                float d = exp2f(binf * KM);
                float sv = seedp[i4+j] - d;
                seedacc = fmaf(sv, sv, seedacc);
                int eb = (NB-1) - min(__float2int_rd(d * (float)NB), NB-1);
                atomicAdd(&mh[eb], 1u);
            }
        }
    }
    __syncthreads();
    for (int i = tid; i < NBU; i += 512){
        unsigned n = hu[i] + hu[NBU + i];
        if (n) atomicAdd(&g_z.uhist[bk][i], n);
    }
    #pragma unroll
    for (int o = 16; o; o >>= 1) seedacc += __shfl_down_sync(0xffffffffu, seedacc, o);
    if ((tid & 31) == 0) s_red[tid>>5] = seedacc;
    __syncthreads();
    if (tid == 0){
        float t = 0.f;
        #pragma unroll
        for (int w = 0; w < 16; w++) t += s_red[w];
        atomicAdd(&g_z.seedloss[b], t);
    }
}

// ---------------------------------------------------------------------------
// Scan: remap u-hist -> err-hist (proportional spreading), suffix scan +
// midpoint Jaccard integration. Last-done CTA finalizes in parallel.
// ---------------------------------------------------------------------------
__global__ void __launch_bounds__(1024) scan_kernel(float* out){
    __shared__ float fn[NB];
    __shared__ float warpN[32], warpG[32];
    __shared__ int s_last;
    __shared__ float s_var[BB], s_pre[BB];
    const int bk = blockIdx.x;
    const int b = bk >> 4;
    const int tid = threadIdx.x, lane = tid & 31, wid = tid >> 5;
    const float G = g_z.cnt[bk];
    const float KD = (UMAX / (float)NBU) * LOG2E;   // d(i) = exp2(-i*KD)

    for (int i = tid; i < NB; i += 1024) fn[i] = 0.f;
    __syncthreads();

    for (int i = tid; i < NBU; i += 1024){
        unsigned c = g_z.uhist[bk][i];
        if (!c) continue;
        float phi = (float)NB * exp2f(-(float)i     * KD);
        float plo = (float)NB * exp2f(-(float)(i+1) * KD);
        phi = fminf(phi, (float)NB - 0.001f);
        plo = fminf(plo, phi);
        float span = phi - plo;
        float fc = (float)c;
        int b1 = (int)phi;
        if (span < 1e-6f){
            atomicAdd(&fn[b1], fc);
        } else {
            int b0 = (int)plo;
            float w = fc / span;
            if (b0 == b1){
                atomicAdd(&fn[b0], fc);
            } else {
                atomicAdd(&fn[b0], w * ((float)(b0+1) - plo));
                for (int bb = b0+1; bb < b1; bb++) atomicAdd(&fn[bb], w);
                atomicAdd(&fn[b1], w * (phi - (float)b1));
            }
        }
    }
    __syncthreads();

    const unsigned* __restrict__ hg = g_z.mhist[bk];
    float lossJ = 0.f, carN = 0.f, carG = 0.f;

    #pragma unroll 1
    for (int c = 0; c < NB/1024; c++){
        int idx = NB - 1 - (c*1024 + tid);
        float n = fn[idx];
        float g = (float)hg[idx];

        float sn = n, sg = g;
        #pragma unroll
        for (int o = 1; o < 32; o <<= 1){
            float tn = __shfl_up_sync(0xffffffffu, sn, o);
            float tg = __shfl_up_sync(0xffffffffu, sg, o);
            if (lane >= o){ sn += tn; sg += tg; }
        }
        if (lane == 31){ warpN[wid] = sn; warpG[wid] = sg; }
        __syncthreads();
        if (wid == 0){
            float wn = warpN[lane], wg = warpG[lane];
            #pragma unroll
            for (int o = 1; o < 32; o <<= 1){
                float tn = __shfl_up_sync(0xffffffffu, wn, o);
                float tg = __shfl_up_sync(0xffffffffu, wg, o);
                if (lane >= o){ wn += tn; wg += tg; }
            }
            warpN[lane] = wn; warpG[lane] = wg;
        }
        __syncthreads();
        float offN = wid ? warpN[wid-1] : 0.f;
        float offG = wid ? warpG[wid-1] : 0.f;
        float totN = warpN[31];
        float totG = warpG[31];
        __syncthreads();

        float cumN = carN + offN + sn;
        float cumG = carG + offG + sg;
        carN += totN;
        carG += totG;

        float nEff = cumN - 0.5f*n;
        float gEff = cumG - 0.5f*g;
        float inter = G - gEff;
        float uni   = G + nEff - gEff;
        lossJ += 1.0f - inter/uni;
    }

    #pragma unroll
    for (int o = 16; o; o >>= 1) lossJ += __shfl_down_sync(0xffffffffu, lossJ, o);
    if (lane == 0) warpN[wid] = lossJ;
    __syncthreads();
    if (tid == 0){
        if (G > 0.f){
            float L = 0.f;
            #pragma unroll
            for (int i = 0; i < 32; i++) L += warpN[i];
            atomicAdd(&g_z.instloss[b], L * (2.0f/NB));
        }
        __threadfence();
        unsigned done = atomicAdd(&g_z.done, 1u);
        s_last = (done == BK - 1) ? 1 : 0;
    }
    __syncthreads();

    if (s_last){
        if (tid < BB){ s_var[tid] = 0.f; s_pre[tid] = 0.f; }
        __syncthreads();
        if (tid < BK){
            float cnt = g_z.cnt[tid];
            if (cnt > 0.f){
                float mn = g_z.ss[tid] / cnt;
                float var = (g_z.ss2[tid] - cnt*mn*mn) / cnt;
                atomicAdd(&s_var[tid>>4], var);
                atomicAdd(&s_pre[tid>>4], 1.f);
            }
        }
        __syncthreads();
        if (tid == 0){
            float tot = 0.f;
            #pragma unroll
            for (int b2 = 0; b2 < BB; b2++){
                float obj = fmaxf(s_pre[b2], 1.0f);
                tot += g_z.instloss[b2] / obj
                     + 10.0f * s_var[b2] / obj
                     + g_z.seedloss[b2] / (float)HW;
            }
            out[0] = tot / (float)BB;
        }
    }
}

// ---------------------------------------------------------------------------
extern "C" void kernel_launch(void* const* d_in, const int* in_sizes, int n_in,
                              void* d_out, int out_size) {
    (void)in_sizes; (void)n_in; (void)out_size;
    const float* pred = (const float*)d_in[0];

    void* zp = nullptr;
    cudaGetSymbolAddress(&zp, g_z);
    cudaMemsetAsync(zp, 0, sizeof(ZeroState), 0);

    dim3 gp(HW/2048, BB);
    prep_kernel<<<gp, 512>>>(pred, d_in[1], d_in[2]);

    dim3 gm(MSPLIT, BK);
    moments_kernel<<<gm, 512>>>(pred);

    lovasz_hist_kernel<<<BK*SPLIT, 512>>>();

    scan_kernel<<<BK, 1024>>>((float*)d_out);
}

// round 15
// speedup vs baseline: 1.0346x; 1.0346x over previous
#include <cuda_runtime.h>
#include <cuda_fp16.h>
#include <math.h>

#define HH 512
#define WW 512
#define BB 8
#define KK 16
#define HW (HH*WW)
#define BK (BB*KK)
#define NBU 1024                 // u-bins (uniform in s*diff^2)
#define NB  1024                 // err-bins (scan space, err coord = d*NB)
#define UMAX 12.0f
#define SPLIT 4
#define MSPLIT 4
#define INV_GRID (1.0f/1023.0f)
#define LOG2E 1.4426950408889634f

// All replay-zeroed state in ONE struct -> one memset node.
struct ZeroState {
    unsigned int uhist[BK][NBU];   // nonmask, u-binned
    unsigned int mhist[BK][NB];    // mask, exact err-binned
    float cnt[BK], scol[BK], srow[BK], ss[BK], ss2[BK];
    float seedloss[BB], instloss[BB];
    unsigned int done;
};
__device__ ZeroState g_z;
__device__ __half2       g_emb[BB*HW];   // (ex, ey) per pixel, f16x2
__device__ float         g_seed[BB*HW];
__device__ unsigned char g_mk[BB*HW];

__device__ __forceinline__ float tanh_fast(float x){
    float y; asm("tanh.approx.f32 %0, %1;" : "=f"(y) : "f"(x)); return y;
}

// ---------------------------------------------------------------------------
// Prep: emb = tanh + xy (stored f16x2), seed = sigmoid, mask byte, bg seed.
// is64 detected inline: odd uint32 words of first 16 int64s all zero <=> int64.
// ---------------------------------------------------------------------------
__global__ void __launch_bounds__(512) prep_kernel(const float* __restrict__ pred,
                                                   const void* __restrict__ instp,
                                                   const void* __restrict__ labp) {
    __shared__ float s_bg[16];
    const int tid = threadIdx.x;
    const int b = blockIdx.y;
    const int i4 = blockIdx.x * 2048 + tid * 4;
    const float* pb = pred + (size_t)b * 4 * HW;
    const size_t off = (size_t)b * HW + i4;

    const unsigned* rr = (const unsigned*)instp;
    unsigned any = 0;
    #pragma unroll
    for (int i = 1; i < 32; i += 2) any |= rr[i];
    const int is64 = any ? 0 : 1;

    float4 p0 = *(const float4*)(pb + i4);
    float4 p1 = *(const float4*)(pb + HW + i4);
    float4 p3 = *(const float4*)(pb + 3*HW + i4);

    int inst[4], lab[4];
    if (is64) {
        const int4* ip = (const int4*)instp;
        const int4* lp = (const int4*)labp;
        size_t q = off >> 1;
        int4 a = ip[q],   c = ip[q+1];
        int4 d0 = lp[q],  d1 = lp[q+1];
        inst[0]=a.x; inst[1]=a.z; inst[2]=c.x; inst[3]=c.z;
        lab[0]=d0.x; lab[1]=d0.z; lab[2]=d1.x; lab[3]=d1.z;
    } else {
        int4 a  = ((const int4*)instp)[off>>2];
        int4 d0 = ((const int4*)labp)[off>>2];
        inst[0]=a.x; inst[1]=a.y; inst[2]=a.z; inst[3]=a.w;
        lab[0]=d0.x; lab[1]=d0.y; lab[2]=d0.z; lab[3]=d0.w;
    }

    float y  = (float)(i4 >> 9) * INV_GRID;
    float xb = (float)(i4 & (WW-1)) * INV_GRID;

    const float* p0a = (const float*)&p0;
    const float* p1a = (const float*)&p1;
    const float* p3a = (const float*)&p3;
    __half2 eh[4];
    float sd[4];
    #pragma unroll
    for (int j = 0; j < 4; j++) {
        float ex = tanh_fast(p0a[j]) + (xb + j*INV_GRID);
        float ey = tanh_fast(p1a[j]) + y;
        eh[j] = __floats2half2_rn(ex, ey);
        sd[j] = fmaf(tanh_fast(0.5f*p3a[j]), 0.5f, 0.5f);
    }
    *(uint4*)(g_emb+off) = *(const uint4*)eh;
    *(float4*)(g_seed+off) = make_float4(sd[0],sd[1],sd[2],sd[3]);

    unsigned mk4 = 0;
    float bg = 0.f;
    #pragma unroll
    for (int j = 0; j < 4; j++) {
        unsigned m = (lab[j]==1 && inst[j]>=1 && inst[j]<=KK) ? (unsigned)inst[j] : 0u;
        mk4 |= m << (8*j);
        if (lab[j]==0) bg += sd[j]*sd[j];
    }
    *(unsigned*)(g_mk+off) = mk4;

    #pragma unroll
    for (int o = 16; o; o >>= 1) bg += __shfl_down_sync(0xffffffffu, bg, o);
    if ((tid & 31) == 0) s_bg[tid>>5] = bg;
    __syncthreads();
    if (tid == 0) {
        float t = 0.f;
        #pragma unroll
        for (int w = 0; w < 16; w++) t += s_bg[w];
        atomicAdd(&g_z.seedloss[b], t);
    }
}

// ---------------------------------------------------------------------------
// Moments: per (b,k), register accumulation, 16 px/thread skip-fast.
// ---------------------------------------------------------------------------
__global__ void __launch_bounds__(512) moments_kernel(const float* __restrict__ pred){
    __shared__ float s_red[16*5];
    const int bk = blockIdx.y;
    const int b = bk >> 4;
    const unsigned kid4 = ((unsigned)(bk & 15) + 1u) * 0x01010101u;
    const int tid = threadIdx.x;
    const float* p2 = pred + (size_t)b*4*HW + 2*HW;
    const unsigned char* mk = g_mk + (size_t)b*HW;
    const int pbase = blockIdx.x * (HW / MSPLIT);

    float cnt=0.f, scol=0.f, srow=0.f, ss=0.f, ss2=0.f;

    #pragma unroll
    for (int g = 0; g < (HW/MSPLIT)/(512*16); g++){   // 8 iterations
        int i16 = pbase + (g*512 + tid)*16;
        uint4 m = *(const uint4*)(mk + i16);
        unsigned e[4];
        e[0] = __vcmpeq4(m.x, kid4); e[1] = __vcmpeq4(m.y, kid4);
        e[2] = __vcmpeq4(m.z, kid4); e[3] = __vcmpeq4(m.w, kid4);
        if (e[0]|e[1]|e[2]|e[3]){
            float row = (float)(i16 >> 9);
            int colb = i16 & (WW-1);
            #pragma unroll
            for (int q = 0; q < 4; q++){
                if (!e[q]) continue;
                #pragma unroll
                for (int j = 0; j < 4; j++){
                    if ((e[q] >> (8*j)) & 1u){
                        int px = q*4 + j;
                        float v = p2[i16+px];
                        cnt += 1.f; scol += (float)(colb+px); srow += row;
                        ss += v; ss2 = fmaf(v, v, ss2);
                    }
                }
            }
        }
    }
    int lane = tid & 31, wid = tid >> 5;
    #pragma unroll
    for (int o = 16; o; o >>= 1){
        cnt += __shfl_down_sync(0xffffffffu,cnt ,o);
        scol+= __shfl_down_sync(0xffffffffu,scol,o);
        srow+= __shfl_down_sync(0xffffffffu,srow,o);
        ss  += __shfl_down_sync(0xffffffffu,ss  ,o);
        ss2 += __shfl_down_sync(0xffffffffu,ss2 ,o);
    }
    if (lane == 0){
        s_red[wid*5+0]=cnt; s_red[wid*5+1]=scol; s_red[wid*5+2]=srow;
        s_red[wid*5+3]=ss;  s_red[wid*5+4]=ss2;
    }
    __syncthreads();
    if (tid == 0){
        float a0=0,a1=0,a2=0,a3=0,a4=0;
        #pragma unroll
        for (int w=0;w<16;w++){a0+=s_red[w*5];a1+=s_red[w*5+1];a2+=s_red[w*5+2];a3+=s_red[w*5+3];a4+=s_red[w*5+4];}
        if (a0 > 0.f){
            atomicAdd(&g_z.cnt[bk], a0); atomicAdd(&g_z.scol[bk], a1);
            atomicAdd(&g_z.srow[bk], a2); atomicAdd(&g_z.ss[bk],  a3);
            atomicAdd(&g_z.ss2[bk],  a4);
        }
    }
}

// ---------------------------------------------------------------------------
// Hist: nonmask -> u-bins via plain smem atomics (single histogram, R13 form);
// mask (~3%) -> exact err-bins via rare global atomics + seed term.
// ---------------------------------------------------------------------------
__global__ void __launch_bounds__(512,4) lovasz_hist_kernel(){
    __shared__ unsigned hu[NBU];
    __shared__ float s_red[16];
    const int bs = blockIdx.x;
    const int bk = bs / SPLIT;
    const int part = bs % SPLIT;
    const int b = bk >> 4;
    const int tid = threadIdx.x;

    for (int i = tid; i < NBU; i += 512) hu[i] = 0u;

    const float cntk = g_z.cnt[bk];
    const float safe = fmaxf(cntk, 1.f);
    const float mean = g_z.ss[bk] / safe;
    const float cx = (g_z.scol[bk] / safe) * INV_GRID;
    const float cy = (g_z.srow[bk] / safe) * INV_GRID;
    const float sE = expf(10.f * mean);
    const float sq  = sqrtf(sE * ((float)NBU / UMAX)); // binf = |e*sq - c*sq|^2
    const float oxs = -cx * sq;
    const float oys = -cy * sq;
    const float KM  = -(UMAX / (float)NBU) * LOG2E;    // d = exp2f(binf*KM)
    const unsigned kid4 = ((unsigned)(bk & 15) + 1u) * 0x01010101u;
    __syncthreads();

    const __half2* __restrict__ emb = g_emb + (size_t)b*HW;
    const float*  __restrict__ seedp= g_seed + (size_t)b*HW;
    const unsigned char* __restrict__ mk = g_mk + (size_t)b*HW;
    unsigned* __restrict__ mh = g_z.mhist[bk];
    const int pbase = part * (HW/SPLIT);
    float seedacc = 0.f;

    #pragma unroll 1
    for (int g = 0; g < (HW/SPLIT)/(512*4); g++){   // 32 iterations
        int i4 = pbase + (g*512 + tid)*4;
        uint4 ev = *(const uint4*)(emb + i4);       // 4 px, f16x2 each
        unsigned m4 = *(const unsigned*)(mk + i4);
        unsigned eq = __vcmpeq4(m4, kid4);
        float2 e0 = __half22float2(*(const __half2*)&ev.x);
        float2 e1 = __half22float2(*(const __half2*)&ev.y);
        float2 e2 = __half22float2(*(const __half2*)&ev.z);
        float2 e3 = __half22float2(*(const __half2*)&ev.w);
        float exs[4] = {e0.x, e1.x, e2.x, e3.x};
        float eys[4] = {e0.y, e1.y, e2.y, e3.y};
        #pragma unroll
        for (int j = 0; j < 4; j++){
            float dxs = fmaf(exs[j], sq, oxs);
            float dys = fmaf(eys[j], sq, oys);
            float binf = fmaf(dxs, dxs, dys*dys);
            if (!((eq >> (8*j)) & 1u)){
                int bin = min((int)binf, NBU-1);
                atomicAdd(&hu[bin], 1u);
            } else {
                float d = exp2f(binf * KM);
                float sv = seedp[i4+j] - d;
                seedacc = fmaf(sv, sv, seedacc);
                int eb = (NB-1) - min(__float2int_rd(d * (float)NB), NB-1);
                atomicAdd(&mh[eb], 1u);
            }
        }
    }
    __syncthreads();
    for (int i = tid; i < NBU; i += 512){
        unsigned n = hu[i]; if (n) atomicAdd(&g_z.uhist[bk][i], n);
    }
    #pragma unroll
    for (int o = 16; o; o >>= 1) seedacc += __shfl_down_sync(0xffffffffu, seedacc, o);
    if ((tid & 31) == 0) s_red[tid>>5] = seedacc;
    __syncthreads();
    if (tid == 0){
        float t = 0.f;
        #pragma unroll
        for (int w = 0; w < 16; w++) t += s_red[w];
        atomicAdd(&g_z.seedloss[b], t);
    }
}

// ---------------------------------------------------------------------------
// Scan: remap u-hist -> err-hist (proportional spreading), suffix scan +
// midpoint Jaccard integration (single 1024-bin chunk now).
// Last-done CTA finalizes in parallel.
// ---------------------------------------------------------------------------
__global__ void __launch_bounds__(1024) scan_kernel(float* out){
    __shared__ float fn[NB];
    __shared__ float warpN[32], warpG[32];
    __shared__ int s_last;
    __shared__ float s_var[BB], s_pre[BB];
    const int bk = blockIdx.x;
    const int b = bk >> 4;
    const int tid = threadIdx.x, lane = tid & 31, wid = tid >> 5;
    const float G = g_z.cnt[bk];
    const float KD = (UMAX / (float)NBU) * LOG2E;   // d(i) = exp2(-i*KD)

    for (int i = tid; i < NB; i += 1024) fn[i] = 0.f;
    __syncthreads();

    for (int i = tid; i < NBU; i += 1024){
        unsigned c = g_z.uhist[bk][i];
        if (!c) continue;
        float phi = (float)NB * exp2f(-(float)i     * KD);
        float plo = (float)NB * exp2f(-(float)(i+1) * KD);
        phi = fminf(phi, (float)NB - 0.001f);
        plo = fminf(plo, phi);
        float span = phi - plo;
        float fc = (float)c;
        int b1 = (int)phi;
        if (span < 1e-6f){
            atomicAdd(&fn[b1], fc);
        } else {
            int b0 = (int)plo;
            float w = fc / span;
            if (b0 == b1){
                atomicAdd(&fn[b0], fc);
            } else {
                atomicAdd(&fn[b0], w * ((float)(b0+1) - plo));
                for (int bb = b0+1; bb < b1; bb++) atomicAdd(&fn[bb], w);
                atomicAdd(&fn[b1], w * (phi - (float)b1));
            }
        }
    }
    __syncthreads();

    const unsigned* __restrict__ hg = g_z.mhist[bk];
    float lossJ = 0.f;
    {
        int idx = NB - 1 - tid;
        float n = fn[idx];
        float g = (float)hg[idx];

        float sn = n, sg = g;
        #pragma unroll
        for (int o = 1; o < 32; o <<= 1){
            float tn = __shfl_up_sync(0xffffffffu, sn, o);
            float tg = __shfl_up_sync(0xffffffffu, sg, o);
            if (lane >= o){ sn += tn; sg += tg; }
        }
        if (lane == 31){ warpN[wid] = sn; warpG[wid] = sg; }
        __syncthreads();
        if (wid == 0){
            float wn = warpN[lane], wg = warpG[lane];
            #pragma unroll
            for (int o = 1; o < 32; o <<= 1){
                float tn = __shfl_up_sync(0xffffffffu, wn, o);
                float tg = __shfl_up_sync(0xffffffffu, wg, o);
                if (lane >= o){ wn += tn; wg += tg; }
            }
            warpN[lane] = wn; warpG[lane] = wg;
        }
        __syncthreads();
        float offN = wid ? warpN[wid-1] : 0.f;
        float offG = wid ? warpG[wid-1] : 0.f;

        float cumN = offN + sn;
        float cumG = offG + sg;

        float nEff = cumN - 0.5f*n;
        float gEff = cumG - 0.5f*g;
        float inter = G - gEff;
        float uni   = G + nEff - gEff;
        lossJ = 1.0f - inter/uni;
    }

    #pragma unroll
    for (int o = 16; o; o >>= 1) lossJ += __shfl_down_sync(0xffffffffu, lossJ, o);
    __syncthreads();
    if (lane == 0) warpN[wid] = lossJ;
    __syncthreads();
    if (tid == 0){
        if (G > 0.f){
            float L = 0.f;
            #pragma unroll
            for (int i = 0; i < 32; i++) L += warpN[i];
            atomicAdd(&g_z.instloss[b], L * (2.0f/NB));
        }
        __threadfence();
        unsigned done = atomicAdd(&g_z.done, 1u);
        s_last = (done == BK - 1) ? 1 : 0;
    }
    __syncthreads();

    if (s_last){
        if (tid < BB){ s_var[tid] = 0.f; s_pre[tid] = 0.f; }
        __syncthreads();
        if (tid < BK){
            float cnt = g_z.cnt[tid];
            if (cnt > 0.f){
                float mn = g_z.ss[tid] / cnt;
                float var = (g_z.ss2[tid] - cnt*mn*mn) / cnt;
                atomicAdd(&s_var[tid>>4], var);
                atomicAdd(&s_pre[tid>>4], 1.f);
            }
        }
        __syncthreads();
        if (tid == 0){
            float tot = 0.f;
            #pragma unroll
            for (int b2 = 0; b2 < BB; b2++){
                float obj = fmaxf(s_pre[b2], 1.0f);
                tot += g_z.instloss[b2] / obj
                     + 10.0f * s_var[b2] / obj
                     + g_z.seedloss[b2] / (float)HW;
            }
            out[0] = tot / (float)BB;
        }
    }
}

// ---------------------------------------------------------------------------
extern "C" void kernel_launch(void* const* d_in, const int* in_sizes, int n_in,
                              void* d_out, int out_size) {
    (void)in_sizes; (void)n_in; (void)out_size;
    const float* pred = (const float*)d_in[0];

    void* zp = nullptr;
    cudaGetSymbolAddress(&zp, g_z);
    cudaMemsetAsync(zp, 0, sizeof(ZeroState), 0);

    dim3 gp(HW/2048, BB);
    prep_kernel<<<gp, 512>>>(pred, d_in[1], d_in[2]);

    dim3 gm(MSPLIT, BK);
    moments_kernel<<<gm, 512>>>(pred);

    lovasz_hist_kernel<<<BK*SPLIT, 512>>>();

    scan_kernel<<<BK, 1024>>>((float*)d_out);
}